// round 4
// baseline (speedup 1.0000x reference)
#include <cuda_runtime.h>
#include <cstdint>

// C[2048,4096] = A[2048,4096] @ W[4096,4096]^T + bias
// W dequantized from 4-bit codebook codes.
// GEMM via warp-level mma.sync tf32 (tcgen05 is feature-gated off by the
// harness's compute_103 PTX target).
// R4: 3-stage cp.async pipeline (1 barrier/iter), A rounded in-register
// (aconv kernel removed).

constexpr int KDIM = 4096;
constexpr int NDIM = 4096;
constexpr int MDIM = 2048;

__device__ float g_W[(size_t)NDIM * KDIM];   // dequantized, tf32-rounded

__device__ __forceinline__ float to_tf32(float v) {
    uint32_t b;
    asm("cvt.rna.tf32.f32 %0, %1;" : "=r"(b) : "f"(v));
    return __uint_as_float(b);
}
__device__ __forceinline__ uint32_t to_tf32_u(float v) {
    uint32_t b;
    asm("cvt.rna.tf32.f32 %0, %1;" : "=r"(b) : "f"(v));
    return b;
}

// ---------------------------------------------------------------------------
// Phase 1: dequantize W (one row per block), store tf32-rounded.
// ---------------------------------------------------------------------------
__global__ void dequant_kernel(const float* __restrict__ codebooks,
                               const int* __restrict__ codes) {
    const int r = blockIdx.x;
    __shared__ float cb[512];
    const float* cbr = codebooks + (size_t)r * 512;
    for (int i = threadIdx.x; i < 512; i += 256) cb[i] = cbr[i];
    __syncthreads();

    const int4* codes_r = (const int4*)(codes + (size_t)r * KDIM);
    float4* w_r = (float4*)(g_W + (size_t)r * KDIM);
    #pragma unroll
    for (int it = 0; it < 4; it++) {
        int i = threadIdx.x + it * 256;
        int4 c = codes_r[i];
        const float* cbg = cb + ((i >> 5) << 4);
        w_r[i] = make_float4(to_tf32(cbg[c.x]), to_tf32(cbg[c.y]),
                             to_tf32(cbg[c.z]), to_tf32(cbg[c.w]));
    }
}

// ---------------------------------------------------------------------------
// Phase 2: tf32 mma.sync GEMM. Block 128x256x32, 8 warps, warp tile 64x64.
// 3-stage cp.async pipeline, one __syncthreads per K-iter.
// ---------------------------------------------------------------------------
constexpr int BM = 128, BN = 256, BK = 32;
constexpr int STRIDE = BK + 4;                       // 36 floats
constexpr int A_STAGE = BM * STRIDE;                 // 4608 floats
constexpr int B_STAGE = BN * STRIDE;                 // 9216 floats
constexpr int STAGE   = A_STAGE + B_STAGE;           // 13824 floats
constexpr int NSTAGE  = 3;
constexpr int SMEM_DYN = STAGE * NSTAGE * 4;         // 165888 bytes
constexpr int KITERS = KDIM / BK;                    // 128

extern __shared__ float smf[];

__device__ __forceinline__ uint32_t smem_u32(const void* p) {
    uint32_t a;
    asm("{ .reg .u64 t; cvta.to.shared.u64 t, %1; cvt.u32.u64 %0, t; }"
        : "=r"(a) : "l"(p));
    return a;
}

__device__ __forceinline__ void cp_async16(uint32_t dst, const void* src) {
    asm volatile("cp.async.cg.shared.global [%0], [%1], 16;"
                 :: "r"(dst), "l"(src));
}

__device__ __forceinline__ void mma_tf32(float* c, const uint32_t* a,
                                         const uint32_t* b) {
    asm volatile(
        "mma.sync.aligned.m16n8k8.row.col.f32.tf32.tf32.f32 "
        "{%0,%1,%2,%3}, {%4,%5,%6,%7}, {%8,%9}, {%0,%1,%2,%3};"
        : "+f"(c[0]), "+f"(c[1]), "+f"(c[2]), "+f"(c[3])
        : "r"(a[0]), "r"(a[1]), "r"(a[2]), "r"(a[3]), "r"(b[0]), "r"(b[1]));
}

__device__ __forceinline__ void load_tile(uint32_t sbase,
                                          const float* __restrict__ Ab,
                                          const float* __restrict__ Bb,
                                          int k0, int tid) {
    // A: 128 rows x 8 float4; 1024 chunks, 4/thread
    #pragma unroll
    for (int j = 0; j < 4; j++) {
        int i = tid + j * 256;
        int row = i >> 3, ci = (i & 7) * 4;
        cp_async16(sbase + (uint32_t)(row * STRIDE + ci) * 4,
                   Ab + (size_t)row * KDIM + k0 + ci);
    }
    // B: 256 rows x 8 float4; 2048 chunks, 8/thread
    const uint32_t sb = sbase + A_STAGE * 4;
    #pragma unroll
    for (int j = 0; j < 8; j++) {
        int i = tid + j * 256;
        int row = i >> 3, ci = (i & 7) * 4;
        cp_async16(sb + (uint32_t)(row * STRIDE + ci) * 4,
                   Bb + (size_t)row * KDIM + k0 + ci);
    }
    asm volatile("cp.async.commit_group;" ::: "memory");
}

__global__ void __launch_bounds__(256, 1)
gemm_mma_kernel(const float* __restrict__ A,
                const float* __restrict__ bias,
                float* __restrict__ C) {
    const int tid  = threadIdx.x;
    const int wid  = tid >> 5;
    const int lane = tid & 31;
    const int gid  = lane >> 2;      // group of 4
    const int tig  = lane & 3;       // thread in group

    const int m0 = blockIdx.y * BM;
    const int n0 = blockIdx.x * BN;
    const int wm = (wid >> 2) * 64;  // warp grid 2(M) x 4(N), tile 64x64
    const int wn = (wid & 3) * 64;

    const uint32_t smem_base = smem_u32(smf);
    const float* Ab = A   + (size_t)m0 * KDIM;   // raw fp32 x; rounded at use
    const float* Bb = g_W + (size_t)n0 * KDIM;   // pre-rounded tf32

    float acc[4][8][4] = {};

    // prologue: stages 0 and 1 in flight
    load_tile(smem_base,                 Ab, Bb, 0,  tid);
    load_tile(smem_base + STAGE * 4,     Ab, Bb, BK, tid);

    for (int it = 0; it < KITERS; it++) {
        // stage `it` must be complete locally
        if (it + 1 < KITERS) {
            asm volatile("cp.async.wait_group 1;" ::: "memory");
        } else {
            asm volatile("cp.async.wait_group 0;" ::: "memory");
        }
        // everyone's copies for stage `it` landed; everyone done reading it-1
        __syncthreads();

        // issue loads for it+2 into the stage freed at iter it-1
        if (it + 2 < KITERS) {
            load_tile(smem_base + (uint32_t)((it + 2) % NSTAGE) * STAGE * 4,
                      Ab, Bb, (it + 2) * BK, tid);
        }

        const float* sA = smf + (it % NSTAGE) * STAGE;
        const float* sB = sA + A_STAGE;

        #pragma unroll
        for (int ks = 0; ks < 4; ks++) {
            const int kb = ks * 8;
            uint32_t af[4][4], bf[8][2];
            #pragma unroll
            for (int mt = 0; mt < 4; mt++) {
                const float* p = sA + (wm + mt * 16 + gid) * STRIDE + kb + tig;
                af[mt][0] = to_tf32_u(p[0]);
                af[mt][1] = to_tf32_u(p[8 * STRIDE]);
                af[mt][2] = to_tf32_u(p[4]);
                af[mt][3] = to_tf32_u(p[8 * STRIDE + 4]);
            }
            #pragma unroll
            for (int nt = 0; nt < 8; nt++) {
                const float* p = sB + (wn + nt * 8 + gid) * STRIDE + kb + tig;
                bf[nt][0] = __float_as_uint(p[0]);
                bf[nt][1] = __float_as_uint(p[4]);
            }
            #pragma unroll
            for (int mt = 0; mt < 4; mt++)
                #pragma unroll
                for (int nt = 0; nt < 8; nt++)
                    mma_tf32(acc[mt][nt], af[mt], bf[nt]);
        }
    }

    // epilogue: bias + store
    #pragma unroll
    for (int mt = 0; mt < 4; mt++) {
        #pragma unroll
        for (int nt = 0; nt < 8; nt++) {
            const int r0 = m0 + wm + mt * 16 + gid;
            const int c  = n0 + wn + nt * 8 + tig * 2;
            const float2 b2 = *(const float2*)(bias + c);
            float2 o0, o1;
            o0.x = acc[mt][nt][0] + b2.x;
            o0.y = acc[mt][nt][1] + b2.y;
            o1.x = acc[mt][nt][2] + b2.x;
            o1.y = acc[mt][nt][3] + b2.y;
            *(float2*)(C + (size_t)r0 * NDIM + c)       = o0;
            *(float2*)(C + (size_t)(r0 + 8) * NDIM + c) = o1;
        }
    }
}

// ---------------------------------------------------------------------------
extern "C" void kernel_launch(void* const* d_in, const int* in_sizes, int n_in,
                              void* d_out, int out_size) {
    const float* x         = (const float*)d_in[0];
    const float* codebooks = (const float*)d_in[1];
    const int*   codes     = (const int*)d_in[2];
    const float* bias      = (const float*)d_in[3];
    float* out = (float*)d_out;

    dequant_kernel<<<NDIM, 256>>>(codebooks, codes);

    cudaFuncSetAttribute(gemm_mma_kernel,
                         cudaFuncAttributeMaxDynamicSharedMemorySize, SMEM_DYN);
    dim3 grid(NDIM / BN, MDIM / BM);   // (16, 16)
    gemm_mma_kernel<<<grid, 256, SMEM_DYN>>>(x, bias, out);
}